// round 12
// baseline (speedup 1.0000x reference)
#include <cuda_runtime.h>
#include <cuda_fp16.h>
#include <mma.h>
#include <math.h>

using namespace nvcuda;

// ---------------- static config ----------------
#define T_TOK   2048
#define HID     2048
#define MOE_I   1024
#define SH_I    4096
#define NEXP    16
#define MAX_TILES 48
#define MAX_ROWS (MAX_TILES*128)

// ---------------- device scratch ----------------
__device__ int    g_topk_idx[T_TOK*2];
__device__ float  g_topk_w[T_TOK*2];
__device__ int    g_off[NEXP];
__device__ int    g_ntiles;
__device__ int    g_tileE[MAX_TILES];
__device__ int    g_tileM0[MAX_TILES];
__device__ int    g_perm[MAX_ROWS];
__device__ float  g_pw[MAX_ROWS];
__device__ __half g_X16[(size_t)T_TOK*HID];
__device__ __half g_XG[(size_t)MAX_ROWS*HID];
__device__ __half g_Act[(size_t)MAX_ROWS*MOE_I];
__device__ __half g_ActS[(size_t)T_TOK*SH_I];
__device__ __half g_wu16[(size_t)NEXP*HID*MOE_I];
__device__ __half g_wd16[(size_t)NEXP*MOE_I*HID];
__device__ __half g_su16[(size_t)HID*SH_I];
__device__ __half g_sd16[(size_t)SH_I*HID];

// ---------------- fp32 -> fp16 weight conversion ----------------
__global__ __launch_bounds__(256) void cvtw_kernel(const float* __restrict__ src,
                                                   __half* __restrict__ dst, int n8)
{
    int i = blockIdx.x * 256 + threadIdx.x;
    if (i >= n8) return;
    const float4* s = (const float4*)src + (size_t)i * 2;
    float4 a = s[0], b = s[1];
    __half2 h[4];
    h[0] = __floats2half2_rn(a.x, a.y);
    h[1] = __floats2half2_rn(a.z, a.w);
    h[2] = __floats2half2_rn(b.x, b.y);
    h[3] = __floats2half2_rn(b.z, b.w);
    *(uint4*)(dst + (size_t)i * 8) = *(uint4*)h;
}

// ---------------- router (fp32, exact replica of reference routing) ----------------
__global__ __launch_bounds__(128) void router_kernel(
    const float* __restrict__ x, const float* __restrict__ wr,
    const float* __restrict__ eb)
{
    int warp = threadIdx.x >> 5;
    int lane = threadIdx.x & 31;
    int t = blockIdx.x * 4 + warp;
    const float* xr = x + (size_t)t * HID;

    float xv[64];
#pragma unroll
    for (int i = 0; i < 64; i++) xv[i] = xr[lane + 32 * i];

    float sc[NEXP];
#pragma unroll
    for (int e = 0; e < NEXP; e++) {
        const float* w = wr + (size_t)e * HID;
        float s = 0.f;
#pragma unroll
        for (int i = 0; i < 64; i++) s += xv[i] * w[lane + 32 * i];
#pragma unroll
        for (int o = 16; o > 0; o >>= 1) s += __shfl_xor_sync(0xffffffffu, s, o);
        sc[e] = s;
    }

    if (lane == 0) {
        float raw[NEXP], sb[NEXP];
#pragma unroll
        for (int e = 0; e < NEXP; e++) {
            raw[e] = 1.f / (1.f + expf(-sc[e]));
            sb[e]  = raw[e] + eb[e];
        }
        float gs[4];
#pragma unroll
        for (int g = 0; g < 4; g++) {
            float m1 = -1e30f, m2 = -1e30f;
#pragma unroll
            for (int j = 0; j < 4; j++) {
                float v = sb[4 * g + j];
                if (v > m1) { m2 = m1; m1 = v; }
                else if (v > m2) m2 = v;
            }
            gs[g] = m1 + m2;
        }
        int g1 = 0;
        for (int g = 1; g < 4; g++) if (gs[g] > gs[g1]) g1 = g;
        int g2 = -1;
        for (int g = 0; g < 4; g++) if (g != g1 && (g2 < 0 || gs[g] > gs[g2])) g2 = g;
        float masked[NEXP];
#pragma unroll
        for (int e = 0; e < NEXP; e++) {
            int grp = e >> 2;
            masked[e] = (grp == g1 || grp == g2) ? sb[e] : 0.f;
        }
        int e1 = 0;
        for (int e = 1; e < NEXP; e++) if (masked[e] > masked[e1]) e1 = e;
        int e2 = -1;
        for (int e = 0; e < NEXP; e++) if (e != e1 && (e2 < 0 || masked[e] > masked[e2])) e2 = e;

        float w1 = raw[e1], w2 = raw[e2];
        float s = w1 + w2 + 1e-20f;
        g_topk_idx[t * 2 + 0] = e1;
        g_topk_idx[t * 2 + 1] = e2;
        g_topk_w[t * 2 + 0]   = w1 / s;
        g_topk_w[t * 2 + 1]   = w2 / s;
    }
}

// ---------------- scan: parallel histogram + tile table ----------------
__global__ __launch_bounds__(1024) void scan_kernel()
{
    __shared__ int cnt[NEXP];
    int tid = threadIdx.x;
    if (tid < NEXP) cnt[tid] = 0;
    __syncthreads();
    for (int i = tid; i < T_TOK * 2; i += 1024)
        atomicAdd(&cnt[g_topk_idx[i]], 1);
    __syncthreads();
    if (tid == 0) {
        int off = 0, nt = 0;
        for (int ee = 0; ee < NEXP; ee++) {
            g_off[ee] = off;
            int tiles = (cnt[ee] + 127) / 128;
            for (int tt = 0; tt < tiles; tt++) {
                g_tileE[nt]  = ee;
                g_tileM0[nt] = off + tt * 128;
                nt++;
            }
            off += tiles * 128;
        }
        g_ntiles = nt;
        for (int i = nt; i < MAX_TILES; i++) { g_tileE[i] = -1; g_tileM0[i] = 0; }
    }
}

// ---------------- gather ----------------
__global__ __launch_bounds__(256) void gather_kernel()
{
    int e = blockIdx.x;
    int base = g_off[e];
    int tid = threadIdx.x, lane = tid & 31, wid = tid >> 5;
    __shared__ int warpTot[8];
    int written = 0;

    for (int chunk = 0; chunk < T_TOK; chunk += 256) {
        int t = chunk + tid;
        int i0 = g_topk_idx[t * 2], i1 = g_topk_idx[t * 2 + 1];
        int which = (i0 == e) ? 0 : ((i1 == e) ? 1 : -1);
        unsigned b = __ballot_sync(0xffffffffu, which >= 0);
        int wpre = __popc(b & ((1u << lane) - 1));
        if (lane == 0) warpTot[wid] = __popc(b);
        __syncthreads();
        int woff = 0;
        for (int w = 0; w < wid; w++) woff += warpTot[w];
        if (which >= 0) {
            int pos = base + written + woff + wpre;
            g_perm[pos] = t;
            g_pw[pos]   = g_topk_w[t * 2 + which];
        }
        int tot = 0;
        for (int w = 0; w < 8; w++) tot += warpTot[w];
        written += tot;
        __syncthreads();
    }
    int padEnd = base + ((written + 127) / 128) * 128;
    for (int i = base + written + tid; i < padEnd; i += 256) {
        g_perm[i] = 0;
        g_pw[i]   = 0.f;
    }
}

// ---------------- token fp32->fp16 and gather ----------------
__global__ __launch_bounds__(256) void convx_kernel(const float* __restrict__ x)
{
    int row = blockIdx.x;
    int c0 = threadIdx.x * 8;
    const float* src = x + (size_t)row * HID + c0;
    float4 a = *(const float4*)src;
    float4 b = *(const float4*)(src + 4);
    __half2 h[4];
    h[0] = __floats2half2_rn(a.x, a.y);
    h[1] = __floats2half2_rn(a.z, a.w);
    h[2] = __floats2half2_rn(b.x, b.y);
    h[3] = __floats2half2_rn(b.z, b.w);
    *(uint4*)(g_X16 + (size_t)row * HID + c0) = *(uint4*)h;
}

__global__ __launch_bounds__(256) void gatherx_kernel()
{
    int row = blockIdx.x;
    int t = g_perm[row];
    int c0 = threadIdx.x * 8;
    *(uint4*)(g_XG + (size_t)row * HID + c0) =
        *(const uint4*)(g_X16 + (size_t)t * HID + c0);
}

// ---------------- pipelined wmma GEMM: 128x256 CTA tile, 8 warps (64x64 each) ----------------
// MODE 0: shared up   : X16  x su16 -> relu^2 -> ActS
// MODE 1: shared down : ActS x sd16 -> out (store)
// MODE 2: routed up   : XG   x wu16[e] -> relu^2 * pw -> Act
// MODE 3: routed down : Act  x wd16[e] -> atomicAdd out
#define BM 128
#define BN 256
#define BK 32
#define STAGES 4
#define A_PITCH 40                                  // 32 + 8 halves
#define B_PITCH 264                                 // 256 + 8 halves
#define A_ST_HALVES (BM * A_PITCH)                  // 5120
#define B_ST_HALVES (BK * B_PITCH)                  // 8448
#define STAGE_HALVES (A_ST_HALVES + B_ST_HALVES)    // 13568
#define GEMM_SMEM_BYTES (STAGES * STAGE_HALVES * 2) // 108544

__device__ __forceinline__ void cp16(__half* smem, const __half* gmem)
{
    unsigned s = (unsigned)__cvta_generic_to_shared(smem);
    asm volatile("cp.async.cg.shared.global [%0], [%1], 16;\n" :: "r"(s), "l"(gmem));
}

template<int MODE>
__global__ __launch_bounds__(256) void gemm_kernel(const __half* __restrict__ Wb,
                                                   float* __restrict__ out)
{
    constexpr int K = (MODE == 0 || MODE == 2) ? 2048 : (MODE == 1 ? 4096 : 1024);
    constexpr int N = (MODE == 0) ? 4096 : (MODE == 2 ? 1024 : 2048);
    constexpr int KT = K / BK;

    int m0;
    const __half* Bg;
    if (MODE == 2 || MODE == 3) {
        int tile = blockIdx.y;
        if (tile >= g_ntiles) return;
        m0 = g_tileM0[tile];
        Bg = Wb + (size_t)g_tileE[tile] * HID * MOE_I;
    } else {
        m0 = blockIdx.y * BM;
        Bg = Wb;
    }
    int n0 = blockIdx.x * BN;

    const __half* Ag;
    if (MODE == 0) Ag = g_X16 + (size_t)m0 * K;
    if (MODE == 1) Ag = g_ActS + (size_t)m0 * K;
    if (MODE == 2) Ag = g_XG  + (size_t)m0 * K;
    if (MODE == 3) Ag = g_Act + (size_t)m0 * K;

    extern __shared__ __align__(16) char smem[];
    __half* sh = (__half*)smem;

    int tid = threadIdx.x;
    int wid = tid >> 5;
    int wm = wid >> 2, wn = wid & 3;   // 2x4 warp grid, 64x64 per warp

    wmma::fragment<wmma::accumulator, 16, 16, 16, float> acc[4][4];
#pragma unroll
    for (int i = 0; i < 4; i++)
#pragma unroll
        for (int j = 0; j < 4; j++) wmma::fill_fragment(acc[i][j], 0.f);

    auto load_stage = [&](int s, int k0) {
        __half* As = sh + s * STAGE_HALVES;
        __half* Bs = As + A_ST_HALVES;
        // A: 128 rows x 32 halves = 512 x 16B chunks
#pragma unroll
        for (int l = 0; l < 2; l++) {
            int i = tid + l * 256;
            int r = i >> 2, c8 = (i & 3) * 8;
            cp16(As + r * A_PITCH + c8, Ag + (size_t)r * K + k0 + c8);
        }
        // B: 32 rows x 256 halves = 1024 x 16B chunks
#pragma unroll
        for (int l = 0; l < 4; l++) {
            int i = tid + l * 256;
            int r = i >> 5, c8 = (i & 31) * 8;
            cp16(Bs + r * B_PITCH + c8, Bg + (size_t)(k0 + r) * N + n0 + c8);
        }
        asm volatile("cp.async.commit_group;\n");
    };

    load_stage(0, 0);
    load_stage(1, BK);
    load_stage(2, 2 * BK);

    for (int kt = 0; kt < KT; kt++) {
        if (kt + 3 < KT) asm volatile("cp.async.wait_group 2;\n");
        else if (kt + 2 < KT) asm volatile("cp.async.wait_group 1;\n");
        else asm volatile("cp.async.wait_group 0;\n");
        __syncthreads();
        if (kt + 3 < KT) load_stage((kt + 3) % STAGES, (kt + 3) * BK);

        __half* As = sh + (kt % STAGES) * STAGE_HALVES;
        __half* Bs = As + A_ST_HALVES;
#pragma unroll
        for (int kk = 0; kk < BK; kk += 16) {
            wmma::fragment<wmma::matrix_a, 16, 16, 16, __half, wmma::row_major> af[4];
            wmma::fragment<wmma::matrix_b, 16, 16, 16, __half, wmma::row_major> bf[4];
#pragma unroll
            for (int i = 0; i < 4; i++)
                wmma::load_matrix_sync(af[i], As + (wm * 64 + i * 16) * A_PITCH + kk, A_PITCH);
#pragma unroll
            for (int j = 0; j < 4; j++)
                wmma::load_matrix_sync(bf[j], Bs + kk * B_PITCH + wn * 64 + j * 16, B_PITCH);
#pragma unroll
            for (int i = 0; i < 4; i++)
#pragma unroll
                for (int j = 0; j < 4; j++)
                    wmma::mma_sync(acc[i][j], af[i], bf[j], acc[i][j]);
        }
        __syncthreads();
    }

    // epilogue in two 128-col halves via shared (reuse pipeline smem)
    float* Cs = (float*)smem;
#pragma unroll
    for (int h = 0; h < 2; h++) {
        __syncthreads();
        if ((wn >> 1) == h) {
#pragma unroll
            for (int i = 0; i < 4; i++)
#pragma unroll
                for (int j = 0; j < 4; j++)
                    wmma::store_matrix_sync(
                        Cs + (wm * 64 + i * 16) * 132 + (wn & 1) * 64 + j * 16,
                        acc[i][j], 132, wmma::mem_row_major);
        }
        __syncthreads();
#pragma unroll
        for (int l = 0; l < 64; l++) {
            int i = tid + l * 256;          // 16384 = 128x128
            int r = i >> 7, c = i & 127;
            float v = Cs[r * 132 + c];
            int R = m0 + r;
            int C = n0 + h * 128 + c;
            if (MODE == 0) {
                float rl = fmaxf(v, 0.f);
                g_ActS[(size_t)R * SH_I + C] = __float2half(rl * rl);
            }
            if (MODE == 1) {
                out[(size_t)R * HID + C] = v;
            }
            if (MODE == 2) {
                float rl = fmaxf(v, 0.f);
                g_Act[(size_t)R * MOE_I + C] = __float2half(rl * rl * g_pw[R]);
            }
            if (MODE == 3) {
                atomicAdd(out + (size_t)g_perm[R] * HID + C, v);
            }
        }
    }
}

// ---------------- launch ----------------
extern "C" void kernel_launch(void* const* d_in, const int* in_sizes, int n_in,
                              void* d_out, int out_size)
{
    const float* x  = (const float*)d_in[0];
    const float* wr = (const float*)d_in[1];
    const float* eb = (const float*)d_in[2];
    const float* wu = (const float*)d_in[3];
    const float* wd = (const float*)d_in[4];
    const float* su = (const float*)d_in[5];
    const float* sd = (const float*)d_in[6];
    float* out = (float*)d_out;

    cudaFuncSetAttribute(gemm_kernel<0>, cudaFuncAttributeMaxDynamicSharedMemorySize, GEMM_SMEM_BYTES);
    cudaFuncSetAttribute(gemm_kernel<1>, cudaFuncAttributeMaxDynamicSharedMemorySize, GEMM_SMEM_BYTES);
    cudaFuncSetAttribute(gemm_kernel<2>, cudaFuncAttributeMaxDynamicSharedMemorySize, GEMM_SMEM_BYTES);
    cudaFuncSetAttribute(gemm_kernel<3>, cudaFuncAttributeMaxDynamicSharedMemorySize, GEMM_SMEM_BYTES);

    __half* wu16p; cudaGetSymbolAddress((void**)&wu16p, g_wu16);
    __half* wd16p; cudaGetSymbolAddress((void**)&wd16p, g_wd16);
    __half* su16p; cudaGetSymbolAddress((void**)&su16p, g_su16);
    __half* sd16p; cudaGetSymbolAddress((void**)&sd16p, g_sd16);

    // ordered so launch index 5 is gemm<0> (for ncu -s 5 -c 1 capture)
    cvtw_kernel<<<4096, 256>>>(su, su16p, HID * SH_I / 8);            // 0
    router_kernel<<<T_TOK / 4, 128>>>(x, wr, eb);                     // 1
    scan_kernel<<<1, 1024>>>();                                       // 2
    gather_kernel<<<NEXP, 256>>>();                                   // 3
    convx_kernel<<<T_TOK, 256>>>(x);                                  // 4
    gemm_kernel<0><<<dim3(SH_I / BN, T_TOK / BM), 256, GEMM_SMEM_BYTES>>>(su16p, out);  // 5
    gatherx_kernel<<<MAX_ROWS, 256>>>();                              // 6
    cvtw_kernel<<<4096, 256>>>(sd, sd16p, SH_I * HID / 8);            // 7
    gemm_kernel<1><<<dim3(HID / BN, T_TOK / BM), 256, GEMM_SMEM_BYTES>>>(sd16p, out);   // 8
    cvtw_kernel<<<16384, 256>>>(wu, wu16p, NEXP * HID * MOE_I / 8);   // 9
    gemm_kernel<2><<<dim3(MOE_I / BN, MAX_TILES), 256, GEMM_SMEM_BYTES>>>(wu16p, out);  // 10
    cvtw_kernel<<<16384, 256>>>(wd, wd16p, NEXP * MOE_I * HID / 8);   // 11
    gemm_kernel<3><<<dim3(HID / BN, MAX_TILES), 256, GEMM_SMEM_BYTES>>>(wd16p, out);    // 12
}

// round 14
// speedup vs baseline: 1.1603x; 1.1603x over previous
#include <cuda_runtime.h>
#include <cuda_fp16.h>
#include <mma.h>
#include <math.h>

using namespace nvcuda;

// ---------------- static config ----------------
#define T_TOK   2048
#define HID     2048
#define MOE_I   1024
#define SH_I    4096
#define NEXP    16
#define MAX_TILES 48
#define MAX_ROWS (MAX_TILES*128)

// ---------------- device scratch ----------------
__device__ int    g_topk_idx[T_TOK*2];
__device__ float  g_topk_w[T_TOK*2];
__device__ int    g_off[NEXP];
__device__ int    g_ntiles;
__device__ int    g_tileE[MAX_TILES];
__device__ int    g_tileM0[MAX_TILES];
__device__ int    g_perm[MAX_ROWS];
__device__ float  g_pw[MAX_ROWS];
__device__ __half g_X16[(size_t)T_TOK*HID];
__device__ __half g_XG[(size_t)MAX_ROWS*HID];
__device__ __half g_Act[(size_t)MAX_ROWS*MOE_I];
__device__ __half g_ActS[(size_t)T_TOK*SH_I];
__device__ __half g_wu16[(size_t)NEXP*HID*MOE_I];
__device__ __half g_wd16[(size_t)NEXP*MOE_I*HID];
__device__ __half g_su16[(size_t)HID*SH_I];
__device__ __half g_sd16[(size_t)SH_I*HID];

// ---------------- fp32 -> fp16 chunk converter ----------------
__device__ __forceinline__ void cvt_chunk(const float* __restrict__ src,
                                          __half* __restrict__ dst, int i)
{
    const float4* s = (const float4*)src + (size_t)i * 2;
    float4 a = s[0], b = s[1];
    __half2 h[4];
    h[0] = __floats2half2_rn(a.x, a.y);
    h[1] = __floats2half2_rn(a.z, a.w);
    h[2] = __floats2half2_rn(b.x, b.y);
    h[3] = __floats2half2_rn(b.z, b.w);
    *(uint4*)(dst + (size_t)i * 8) = *(uint4*)h;
}

__global__ __launch_bounds__(256) void cvtw_kernel(const float* __restrict__ src,
                                                   __half* __restrict__ dst, int n8)
{
    int i = blockIdx.x * 256 + threadIdx.x;
    if (i < n8) cvt_chunk(src, dst, i);
}

// ---------------- router (fp32, exact replica of reference routing) ----------------
__global__ __launch_bounds__(128) void router_kernel(
    const float* __restrict__ x, const float* __restrict__ wr,
    const float* __restrict__ eb)
{
    int warp = threadIdx.x >> 5;
    int lane = threadIdx.x & 31;
    int t = blockIdx.x * 4 + warp;
    const float* xr = x + (size_t)t * HID;

    float xv[64];
#pragma unroll
    for (int i = 0; i < 64; i++) xv[i] = xr[lane + 32 * i];

    float sc[NEXP];
#pragma unroll
    for (int e = 0; e < NEXP; e++) {
        const float* w = wr + (size_t)e * HID;
        float s = 0.f;
#pragma unroll
        for (int i = 0; i < 64; i++) s += xv[i] * w[lane + 32 * i];
#pragma unroll
        for (int o = 16; o > 0; o >>= 1) s += __shfl_xor_sync(0xffffffffu, s, o);
        sc[e] = s;
    }

    if (lane == 0) {
        float raw[NEXP], sb[NEXP];
#pragma unroll
        for (int e = 0; e < NEXP; e++) {
            raw[e] = 1.f / (1.f + expf(-sc[e]));
            sb[e]  = raw[e] + eb[e];
        }
        float gs[4];
#pragma unroll
        for (int g = 0; g < 4; g++) {
            float m1 = -1e30f, m2 = -1e30f;
#pragma unroll
            for (int j = 0; j < 4; j++) {
                float v = sb[4 * g + j];
                if (v > m1) { m2 = m1; m1 = v; }
                else if (v > m2) m2 = v;
            }
            gs[g] = m1 + m2;
        }
        int g1 = 0;
        for (int g = 1; g < 4; g++) if (gs[g] > gs[g1]) g1 = g;
        int g2 = -1;
        for (int g = 0; g < 4; g++) if (g != g1 && (g2 < 0 || gs[g] > gs[g2])) g2 = g;
        float masked[NEXP];
#pragma unroll
        for (int e = 0; e < NEXP; e++) {
            int grp = e >> 2;
            masked[e] = (grp == g1 || grp == g2) ? sb[e] : 0.f;
        }
        int e1 = 0;
        for (int e = 1; e < NEXP; e++) if (masked[e] > masked[e1]) e1 = e;
        int e2 = -1;
        for (int e = 0; e < NEXP; e++) if (e != e1 && (e2 < 0 || masked[e] > masked[e2])) e2 = e;

        float w1 = raw[e1], w2 = raw[e2];
        float s = w1 + w2 + 1e-20f;
        g_topk_idx[t * 2 + 0] = e1;
        g_topk_idx[t * 2 + 1] = e2;
        g_topk_w[t * 2 + 0]   = w1 / s;
        g_topk_w[t * 2 + 1]   = w2 / s;
    }
}

// ---------------- scan: parallel histogram + tile table ----------------
__global__ __launch_bounds__(1024) void scan_kernel()
{
    __shared__ int cnt[NEXP];
    int tid = threadIdx.x;
    if (tid < NEXP) cnt[tid] = 0;
    __syncthreads();
    for (int i = tid; i < T_TOK * 2; i += 1024)
        atomicAdd(&cnt[g_topk_idx[i]], 1);
    __syncthreads();
    if (tid == 0) {
        int off = 0, nt = 0;
        for (int ee = 0; ee < NEXP; ee++) {
            g_off[ee] = off;
            int tiles = (cnt[ee] + 127) / 128;
            for (int tt = 0; tt < tiles; tt++) {
                g_tileE[nt]  = ee;
                g_tileM0[nt] = off + tt * 128;
                nt++;
            }
            off += tiles * 128;
        }
        g_ntiles = nt;
        for (int i = nt; i < MAX_TILES; i++) { g_tileE[i] = -1; g_tileM0[i] = 0; }
    }
}

// ---------------- gather ----------------
__global__ __launch_bounds__(256) void gather_kernel()
{
    int e = blockIdx.x;
    int base = g_off[e];
    int tid = threadIdx.x, lane = tid & 31, wid = tid >> 5;
    __shared__ int warpTot[8];
    int written = 0;

    for (int chunk = 0; chunk < T_TOK; chunk += 256) {
        int t = chunk + tid;
        int i0 = g_topk_idx[t * 2], i1 = g_topk_idx[t * 2 + 1];
        int which = (i0 == e) ? 0 : ((i1 == e) ? 1 : -1);
        unsigned b = __ballot_sync(0xffffffffu, which >= 0);
        int wpre = __popc(b & ((1u << lane) - 1));
        if (lane == 0) warpTot[wid] = __popc(b);
        __syncthreads();
        int woff = 0;
        for (int w = 0; w < wid; w++) woff += warpTot[w];
        if (which >= 0) {
            int pos = base + written + woff + wpre;
            g_perm[pos] = t;
            g_pw[pos]   = g_topk_w[t * 2 + which];
        }
        int tot = 0;
        for (int w = 0; w < 8; w++) tot += warpTot[w];
        written += tot;
        __syncthreads();
    }
    int padEnd = base + ((written + 127) / 128) * 128;
    for (int i = base + written + tid; i < padEnd; i += 256) {
        g_perm[i] = 0;
        g_pw[i]   = 0.f;
    }
}

// ---------------- token fp32->fp16 and gather ----------------
__global__ __launch_bounds__(256) void convx_kernel(const float* __restrict__ x)
{
    int row = blockIdx.x;
    int c0 = threadIdx.x * 8;
    const float* src = x + (size_t)row * HID + c0;
    float4 a = *(const float4*)src;
    float4 b = *(const float4*)(src + 4);
    __half2 h[4];
    h[0] = __floats2half2_rn(a.x, a.y);
    h[1] = __floats2half2_rn(a.z, a.w);
    h[2] = __floats2half2_rn(b.x, b.y);
    h[3] = __floats2half2_rn(b.z, b.w);
    *(uint4*)(g_X16 + (size_t)row * HID + c0) = *(uint4*)h;
}

__global__ __launch_bounds__(256) void gatherx_kernel()
{
    int row = blockIdx.x;
    int t = g_perm[row];
    int c0 = threadIdx.x * 8;
    *(uint4*)(g_XG + (size_t)row * HID + c0) =
        *(const uint4*)(g_X16 + (size_t)t * HID + c0);
}

// ---------------- pipelined wmma GEMM, 2 CTAs/SM, with piggybacked conversion ----------------
// blockIdx.z == 0 : GEMM tile work
// blockIdx.z == 1 : grid-stride fp32->fp16 conversion of the NEXT gemm's weights
// MODE 0: shared up   : X16  x su16 -> relu^2 -> ActS
// MODE 1: shared down : ActS x sd16 -> out (store)
// MODE 2: routed up   : XG   x wu16[e] -> relu^2 * pw -> Act
// MODE 3: routed down : Act  x wd16[e] -> atomicAdd out
#define BM 128
#define BN 128
#define BK 32
#define STAGES 3
#define A_PITCH 40                                  // 32 + 8 halves
#define B_PITCH 136                                 // 128 + 8 halves
#define A_ST_HALVES (BM * A_PITCH)                  // 5120
#define B_ST_HALVES (BK * B_PITCH)                  // 4352
#define STAGE_HALVES (A_ST_HALVES + B_ST_HALVES)    // 9472
#define GEMM_SMEM_BYTES (STAGES * STAGE_HALVES * 2) // 56832 -> 2 CTAs/SM

__device__ __forceinline__ void cp16(__half* smem, const __half* gmem)
{
    unsigned s = (unsigned)__cvta_generic_to_shared(smem);
    asm volatile("cp.async.cg.shared.global [%0], [%1], 16;\n" :: "r"(s), "l"(gmem));
}

template<int MODE>
__global__ __launch_bounds__(256, 2) void gemm_kernel(const __half* __restrict__ Wb,
                                                      float* __restrict__ out,
                                                      const float* __restrict__ csrc,
                                                      __half* __restrict__ cdst,
                                                      int cn8)
{
    constexpr int K = (MODE == 0 || MODE == 2) ? 2048 : (MODE == 1 ? 4096 : 1024);
    constexpr int N = (MODE == 0) ? 4096 : (MODE == 2 ? 1024 : 2048);
    constexpr int KT = K / BK;

    int tid = threadIdx.x;

    // ---- piggyback conversion blocks ----
    if (blockIdx.z == 1) {
        int nb = gridDim.x * gridDim.y;
        int b  = blockIdx.y * gridDim.x + blockIdx.x;
        for (int i = b * 256 + tid; i < cn8; i += nb * 256)
            cvt_chunk(csrc, cdst, i);
        return;
    }

    int m0;
    const __half* Bg;
    if (MODE == 2 || MODE == 3) {
        int tile = blockIdx.y;
        if (tile >= g_ntiles) return;
        m0 = g_tileM0[tile];
        Bg = Wb + (size_t)g_tileE[tile] * HID * MOE_I;
    } else {
        m0 = blockIdx.y * BM;
        Bg = Wb;
    }
    int n0 = blockIdx.x * BN;

    const __half* Ag;
    if (MODE == 0) Ag = g_X16 + (size_t)m0 * K;
    if (MODE == 1) Ag = g_ActS + (size_t)m0 * K;
    if (MODE == 2) Ag = g_XG  + (size_t)m0 * K;
    if (MODE == 3) Ag = g_Act + (size_t)m0 * K;

    extern __shared__ __align__(16) char smem[];
    __half* sh = (__half*)smem;

    int wid = tid >> 5;
    int wm = wid >> 2, wn = wid & 3;   // 2x4 warp grid, 64x32 per warp

    wmma::fragment<wmma::accumulator, 16, 16, 16, float> acc[4][2];
#pragma unroll
    for (int i = 0; i < 4; i++)
#pragma unroll
        for (int j = 0; j < 2; j++) wmma::fill_fragment(acc[i][j], 0.f);

    auto load_stage = [&](int s, int k0) {
        __half* As = sh + s * STAGE_HALVES;
        __half* Bs = As + A_ST_HALVES;
        // A: 128 rows x 32 halves = 512 x 16B chunks
#pragma unroll
        for (int l = 0; l < 2; l++) {
            int i = tid + l * 256;
            int r = i >> 2, c8 = (i & 3) * 8;
            cp16(As + r * A_PITCH + c8, Ag + (size_t)r * K + k0 + c8);
        }
        // B: 32 rows x 128 halves = 512 x 16B chunks
#pragma unroll
        for (int l = 0; l < 2; l++) {
            int i = tid + l * 256;
            int r = i >> 4, c8 = (i & 15) * 8;
            cp16(Bs + r * B_PITCH + c8, Bg + (size_t)(k0 + r) * N + n0 + c8);
        }
        asm volatile("cp.async.commit_group;\n");
    };

    load_stage(0, 0);
    load_stage(1, BK);

    for (int kt = 0; kt < KT; kt++) {
        if (kt + 2 < KT) asm volatile("cp.async.wait_group 1;\n");
        else asm volatile("cp.async.wait_group 0;\n");
        __syncthreads();
        if (kt + 2 < KT) load_stage((kt + 2) % STAGES, (kt + 2) * BK);

        __half* As = sh + (kt % STAGES) * STAGE_HALVES;
        __half* Bs = As + A_ST_HALVES;
#pragma unroll
        for (int kk = 0; kk < BK; kk += 16) {
            wmma::fragment<wmma::matrix_a, 16, 16, 16, __half, wmma::row_major> af[4];
            wmma::fragment<wmma::matrix_b, 16, 16, 16, __half, wmma::row_major> bf[2];
#pragma unroll
            for (int i = 0; i < 4; i++)
                wmma::load_matrix_sync(af[i], As + (wm * 64 + i * 16) * A_PITCH + kk, A_PITCH);
#pragma unroll
            for (int j = 0; j < 2; j++)
                wmma::load_matrix_sync(bf[j], Bs + kk * B_PITCH + wn * 32 + j * 16, B_PITCH);
#pragma unroll
            for (int i = 0; i < 4; i++)
#pragma unroll
                for (int j = 0; j < 2; j++)
                    wmma::mma_sync(acc[i][j], af[i], bf[j], acc[i][j]);
        }
        __syncthreads();
    }

    // epilogue in two 64-col halves via shared (Cs: 128 x 68 floats = 34.8KB)
    float* Cs = (float*)smem;
#pragma unroll
    for (int h = 0; h < 2; h++) {
        __syncthreads();
        if ((wn >> 1) == h) {
#pragma unroll
            for (int i = 0; i < 4; i++)
#pragma unroll
                for (int j = 0; j < 2; j++)
                    wmma::store_matrix_sync(
                        Cs + (wm * 64 + i * 16) * 68 + (wn & 1) * 32 + j * 16,
                        acc[i][j], 68, wmma::mem_row_major);
        }
        __syncthreads();
#pragma unroll
        for (int l = 0; l < 32; l++) {
            int i = tid + l * 256;          // 8192 = 128x64
            int r = i >> 6, c = i & 63;
            float v = Cs[r * 68 + c];
            int R = m0 + r;
            int C = n0 + h * 64 + c;
            if (MODE == 0) {
                float rl = fmaxf(v, 0.f);
                g_ActS[(size_t)R * SH_I + C] = __float2half(rl * rl);
            }
            if (MODE == 1) {
                out[(size_t)R * HID + C] = v;
            }
            if (MODE == 2) {
                float rl = fmaxf(v, 0.f);
                g_Act[(size_t)R * MOE_I + C] = __float2half(rl * rl * g_pw[R]);
            }
            if (MODE == 3) {
                atomicAdd(out + (size_t)g_perm[R] * HID + C, v);
            }
        }
    }
}

// ---------------- launch (single stream, conversions piggybacked) ----------------
extern "C" void kernel_launch(void* const* d_in, const int* in_sizes, int n_in,
                              void* d_out, int out_size)
{
    const float* x  = (const float*)d_in[0];
    const float* wr = (const float*)d_in[1];
    const float* eb = (const float*)d_in[2];
    const float* wu = (const float*)d_in[3];
    const float* wd = (const float*)d_in[4];
    const float* su = (const float*)d_in[5];
    const float* sd = (const float*)d_in[6];
    float* out = (float*)d_out;

    cudaFuncSetAttribute(gemm_kernel<0>, cudaFuncAttributeMaxDynamicSharedMemorySize, GEMM_SMEM_BYTES);
    cudaFuncSetAttribute(gemm_kernel<1>, cudaFuncAttributeMaxDynamicSharedMemorySize, GEMM_SMEM_BYTES);
    cudaFuncSetAttribute(gemm_kernel<2>, cudaFuncAttributeMaxDynamicSharedMemorySize, GEMM_SMEM_BYTES);
    cudaFuncSetAttribute(gemm_kernel<3>, cudaFuncAttributeMaxDynamicSharedMemorySize, GEMM_SMEM_BYTES);

    __half* wu16p; cudaGetSymbolAddress((void**)&wu16p, g_wu16);
    __half* wd16p; cudaGetSymbolAddress((void**)&wd16p, g_wd16);
    __half* su16p; cudaGetSymbolAddress((void**)&su16p, g_su16);
    __half* sd16p; cudaGetSymbolAddress((void**)&sd16p, g_sd16);

    const int n8_su = HID * SH_I / 8;
    const int n8_sd = SH_I * HID / 8;
    const int n8_wu = NEXP * HID * MOE_I / 8;
    const int n8_wd = NEXP * MOE_I * HID / 8;

    // su conversion first (needed by gemm0); everything else piggybacks
    cvtw_kernel<<<4096, 256>>>(su, su16p, n8_su);
    router_kernel<<<T_TOK / 4, 128>>>(x, wr, eb);
    scan_kernel<<<1, 1024>>>();
    gather_kernel<<<NEXP, 256>>>();
    convx_kernel<<<T_TOK, 256>>>(x);
    gatherx_kernel<<<MAX_ROWS, 256>>>();

    // gemm0 (+ convert sd), gemm1 (+ convert wu), gemm2 (+ convert wd), gemm3
    gemm_kernel<0><<<dim3(SH_I / BN, T_TOK / BM, 2), 256, GEMM_SMEM_BYTES>>>(
        su16p, out, sd, sd16p, n8_sd);
    gemm_kernel<1><<<dim3(HID / BN, T_TOK / BM, 2), 256, GEMM_SMEM_BYTES>>>(
        sd16p, out, wu, wu16p, n8_wu);
    gemm_kernel<2><<<dim3(MOE_I / BN, MAX_TILES, 2), 256, GEMM_SMEM_BYTES>>>(
        wu16p, out, wd, wd16p, n8_wd);
    gemm_kernel<3><<<dim3(HID / BN, MAX_TILES, 1), 256, GEMM_SMEM_BYTES>>>(
        wd16p, out, (const float*)nullptr, (__half*)nullptr, 0);
}

// round 16
// speedup vs baseline: 1.1674x; 1.0061x over previous
#include <cuda_runtime.h>
#include <cuda_fp16.h>
#include <mma.h>
#include <math.h>

using namespace nvcuda;

// ---------------- static config ----------------
#define T_TOK   2048
#define HID     2048
#define MOE_I   1024
#define SH_I    4096
#define NEXP    16
#define MAX_TILES 48
#define MAX_ROWS (MAX_TILES*128)

// ---------------- device scratch ----------------
__device__ int    g_topk_idx[T_TOK*2];
__device__ float  g_topk_w[T_TOK*2];
__device__ int    g_ntiles;
__device__ int    g_tileE[MAX_TILES];
__device__ int    g_tileM0[MAX_TILES];
__device__ int    g_perm[MAX_ROWS];
__device__ float  g_pw[MAX_ROWS];
__device__ __half g_X16[(size_t)T_TOK*HID];
__device__ __half g_XG[(size_t)MAX_ROWS*HID];
__device__ __half g_Act[(size_t)MAX_ROWS*MOE_I];
__device__ __half g_ActS[(size_t)T_TOK*SH_I];
__device__ __half g_wu16[(size_t)NEXP*HID*MOE_I];
__device__ __half g_wd16[(size_t)NEXP*MOE_I*HID];
__device__ __half g_su16[(size_t)HID*SH_I];
__device__ __half g_sd16[(size_t)SH_I*HID];

// ---------------- fp32 -> fp16 chunk converter ----------------
__device__ __forceinline__ void cvt_chunk(const float* __restrict__ src,
                                          __half* __restrict__ dst, int i)
{
    const float4* s = (const float4*)src + (size_t)i * 2;
    float4 a = s[0], b = s[1];
    __half2 h[4];
    h[0] = __floats2half2_rn(a.x, a.y);
    h[1] = __floats2half2_rn(a.z, a.w);
    h[2] = __floats2half2_rn(b.x, b.y);
    h[3] = __floats2half2_rn(b.z, b.w);
    *(uint4*)(dst + (size_t)i * 8) = *(uint4*)h;
}

__global__ __launch_bounds__(256) void cvtw_kernel(const float* __restrict__ src,
                                                   __half* __restrict__ dst, int n8)
{
    int i = blockIdx.x * 256 + threadIdx.x;
    if (i < n8) cvt_chunk(src, dst, i);
}

// ---------------- router (fp32, exact replica of reference routing) ----------------
__global__ __launch_bounds__(128) void router_kernel(
    const float* __restrict__ x, const float* __restrict__ wr,
    const float* __restrict__ eb)
{
    int warp = threadIdx.x >> 5;
    int lane = threadIdx.x & 31;
    int t = blockIdx.x * 4 + warp;
    const float* xr = x + (size_t)t * HID;

    float xv[64];
#pragma unroll
    for (int i = 0; i < 64; i++) xv[i] = xr[lane + 32 * i];

    float sc[NEXP];
#pragma unroll
    for (int e = 0; e < NEXP; e++) {
        const float* w = wr + (size_t)e * HID;
        float s = 0.f;
#pragma unroll
        for (int i = 0; i < 64; i++) s += xv[i] * w[lane + 32 * i];
#pragma unroll
        for (int o = 16; o > 0; o >>= 1) s += __shfl_xor_sync(0xffffffffu, s, o);
        sc[e] = s;
    }

    if (lane == 0) {
        float raw[NEXP], sb[NEXP];
#pragma unroll
        for (int e = 0; e < NEXP; e++) {
            raw[e] = 1.f / (1.f + expf(-sc[e]));
            sb[e]  = raw[e] + eb[e];
        }
        float gs[4];
#pragma unroll
        for (int g = 0; g < 4; g++) {
            float m1 = -1e30f, m2 = -1e30f;
#pragma unroll
            for (int j = 0; j < 4; j++) {
                float v = sb[4 * g + j];
                if (v > m1) { m2 = m1; m1 = v; }
                else if (v > m2) m2 = v;
            }
            gs[g] = m1 + m2;
        }
        int g1 = 0;
        for (int g = 1; g < 4; g++) if (gs[g] > gs[g1]) g1 = g;
        int g2 = -1;
        for (int g = 0; g < 4; g++) if (g != g1 && (g2 < 0 || gs[g] > gs[g2])) g2 = g;
        float masked[NEXP];
#pragma unroll
        for (int e = 0; e < NEXP; e++) {
            int grp = e >> 2;
            masked[e] = (grp == g1 || grp == g2) ? sb[e] : 0.f;
        }
        int e1 = 0;
        for (int e = 1; e < NEXP; e++) if (masked[e] > masked[e1]) e1 = e;
        int e2 = -1;
        for (int e = 0; e < NEXP; e++) if (e != e1 && (e2 < 0 || masked[e] > masked[e2])) e2 = e;

        float w1 = raw[e1], w2 = raw[e2];
        float s = w1 + w2 + 1e-20f;
        g_topk_idx[t * 2 + 0] = e1;
        g_topk_idx[t * 2 + 1] = e2;
        g_topk_w[t * 2 + 0]   = w1 / s;
        g_topk_w[t * 2 + 1]   = w2 / s;
    }
}

// ---------------- gather (scan fused: per-block histogram + local base) ----------------
__global__ __launch_bounds__(256) void gather_kernel()
{
    int e = blockIdx.x;
    int tid = threadIdx.x, lane = tid & 31, wid = tid >> 5;
    __shared__ int cnt[NEXP];
    __shared__ int warpTot[8];

    if (tid < NEXP) cnt[tid] = 0;
    __syncthreads();
    for (int i = tid; i < T_TOK * 2; i += 256)
        atomicAdd(&cnt[g_topk_idx[i]], 1);
    __syncthreads();

    // base offset for this expert (padded to 128-row tiles)
    int base = 0;
    for (int ee = 0; ee < NEXP; ee++) {
        if (ee < e) base += ((cnt[ee] + 127) / 128) * 128;
    }

    // block 0 thread 0 writes tile table
    if (e == 0 && tid == 0) {
        int off = 0, nt = 0;
        for (int ee = 0; ee < NEXP; ee++) {
            int tiles = (cnt[ee] + 127) / 128;
            for (int tt = 0; tt < tiles; tt++) {
                g_tileE[nt]  = ee;
                g_tileM0[nt] = off + tt * 128;
                nt++;
            }
            off += tiles * 128;
        }
        g_ntiles = nt;
        for (int i = nt; i < MAX_TILES; i++) { g_tileE[i] = -1; g_tileM0[i] = 0; }
    }

    int written = 0;
    for (int chunk = 0; chunk < T_TOK; chunk += 256) {
        int t = chunk + tid;
        int i0 = g_topk_idx[t * 2], i1 = g_topk_idx[t * 2 + 1];
        int which = (i0 == e) ? 0 : ((i1 == e) ? 1 : -1);
        unsigned b = __ballot_sync(0xffffffffu, which >= 0);
        int wpre = __popc(b & ((1u << lane) - 1));
        if (lane == 0) warpTot[wid] = __popc(b);
        __syncthreads();
        int woff = 0;
        for (int w = 0; w < wid; w++) woff += warpTot[w];
        if (which >= 0) {
            int pos = base + written + woff + wpre;
            g_perm[pos] = t;
            g_pw[pos]   = g_topk_w[t * 2 + which];
        }
        int tot = 0;
        for (int w = 0; w < 8; w++) tot += warpTot[w];
        written += tot;
        __syncthreads();
    }
    int padEnd = base + ((written + 127) / 128) * 128;
    for (int i = base + written + tid; i < padEnd; i += 256) {
        g_perm[i] = 0;
        g_pw[i]   = 0.f;
    }
}

// ---------------- token fp32->fp16 ----------------
__global__ __launch_bounds__(256) void convx_kernel(const float* __restrict__ x)
{
    int row = blockIdx.x;
    int c0 = threadIdx.x * 8;
    const float* src = x + (size_t)row * HID + c0;
    float4 a = *(const float4*)src;
    float4 b = *(const float4*)(src + 4);
    __half2 h[4];
    h[0] = __floats2half2_rn(a.x, a.y);
    h[1] = __floats2half2_rn(a.z, a.w);
    h[2] = __floats2half2_rn(b.x, b.y);
    h[3] = __floats2half2_rn(b.z, b.w);
    *(uint4*)(g_X16 + (size_t)row * HID + c0) = *(uint4*)h;
}

// ---------------- pipelined wmma GEMM, 2 CTAs/SM, piggybacked side-work ----------------
// blockIdx.z == 0 : GEMM tile work
// blockIdx.z == 1 : grid-stride fp32->fp16 conversion of the NEXT gemm's weights
// blockIdx.z == 2 : (gemm0 only) gatherx: g_XG[row] = g_X16[g_perm[row]]
// MODE 0: shared up   : X16  x su16 -> relu^2 -> ActS
// MODE 1: shared down : ActS x sd16 -> out (store)
// MODE 2: routed up   : XG   x wu16[e] -> relu^2 * pw -> Act
// MODE 3: routed down : Act  x wd16[e] -> atomicAdd out
#define BM 128
#define BN 128
#define BK 32
#define STAGES 3
#define A_PITCH 40                                  // 32 + 8 halves
#define B_PITCH 136                                 // 128 + 8 halves
#define A_ST_HALVES (BM * A_PITCH)                  // 5120
#define B_ST_HALVES (BK * B_PITCH)                  // 4352
#define STAGE_HALVES (A_ST_HALVES + B_ST_HALVES)    // 9472
#define GEMM_SMEM_BYTES (STAGES * STAGE_HALVES * 2) // 56832 -> 2 CTAs/SM

__device__ __forceinline__ void cp16(__half* smem, const __half* gmem)
{
    unsigned s = (unsigned)__cvta_generic_to_shared(smem);
    asm volatile("cp.async.cg.shared.global [%0], [%1], 16;\n" :: "r"(s), "l"(gmem));
}

template<int MODE>
__global__ __launch_bounds__(256, 2) void gemm_kernel(const __half* __restrict__ Wb,
                                                      float* __restrict__ out,
                                                      const float* __restrict__ csrc,
                                                      __half* __restrict__ cdst,
                                                      int cn8)
{
    constexpr int K = (MODE == 0 || MODE == 2) ? 2048 : (MODE == 1 ? 4096 : 1024);
    constexpr int N = (MODE == 0) ? 4096 : (MODE == 2 ? 1024 : 2048);
    constexpr int KT = K / BK;

    int tid = threadIdx.x;

    // ---- piggyback: weight conversion ----
    if (blockIdx.z == 1) {
        int nb = gridDim.x * gridDim.y;
        int b  = blockIdx.y * gridDim.x + blockIdx.x;
        for (int i = b * 256 + tid; i < cn8; i += nb * 256)
            cvt_chunk(csrc, cdst, i);
        return;
    }
    // ---- piggyback: gatherx (gemm0 only) ----
    if (blockIdx.z == 2) {
        int nb = gridDim.x * gridDim.y;
        int b  = blockIdx.y * gridDim.x + blockIdx.x;
        int total = MAX_ROWS * (HID / 8);           // uint4 chunks
        for (int i = b * 256 + tid; i < total; i += nb * 256) {
            int row = i >> 8;                       // HID/8 = 256 chunks per row
            int c = i & 255;
            int t = g_perm[row];
            *(uint4*)(g_XG + (size_t)row * HID + c * 8) =
                *(const uint4*)(g_X16 + (size_t)t * HID + c * 8);
        }
        return;
    }

    int m0;
    const __half* Bg;
    if (MODE == 2 || MODE == 3) {
        int tile = blockIdx.y;
        if (tile >= g_ntiles) return;
        m0 = g_tileM0[tile];
        Bg = Wb + (size_t)g_tileE[tile] * HID * MOE_I;
    } else {
        m0 = blockIdx.y * BM;
        Bg = Wb;
    }
    int n0 = blockIdx.x * BN;

    const __half* Ag;
    if (MODE == 0) Ag = g_X16 + (size_t)m0 * K;
    if (MODE == 1) Ag = g_ActS + (size_t)m0 * K;
    if (MODE == 2) Ag = g_XG  + (size_t)m0 * K;
    if (MODE == 3) Ag = g_Act + (size_t)m0 * K;

    extern __shared__ __align__(16) char smem[];
    __half* sh = (__half*)smem;

    int wid = tid >> 5;
    int wm = wid >> 2, wn = wid & 3;   // 2x4 warp grid, 64x32 per warp

    wmma::fragment<wmma::accumulator, 16, 16, 16, float> acc[4][2];
#pragma unroll
    for (int i = 0; i < 4; i++)
#pragma unroll
        for (int j = 0; j < 2; j++) wmma::fill_fragment(acc[i][j], 0.f);

    auto load_stage = [&](int s, int k0) {
        __half* As = sh + s * STAGE_HALVES;
        __half* Bs = As + A_ST_HALVES;
#pragma unroll
        for (int l = 0; l < 2; l++) {
            int i = tid + l * 256;
            int r = i >> 2, c8 = (i & 3) * 8;
            cp16(As + r * A_PITCH + c8, Ag + (size_t)r * K + k0 + c8);
        }
#pragma unroll
        for (int l = 0; l < 2; l++) {
            int i = tid + l * 256;
            int r = i >> 4, c8 = (i & 15) * 8;
            cp16(Bs + r * B_PITCH + c8, Bg + (size_t)(k0 + r) * N + n0 + c8);
        }
        asm volatile("cp.async.commit_group;\n");
    };

    load_stage(0, 0);
    load_stage(1, BK);

    for (int kt = 0; kt < KT; kt++) {
        if (kt + 2 < KT) asm volatile("cp.async.wait_group 1;\n");
        else asm volatile("cp.async.wait_group 0;\n");
        __syncthreads();
        if (kt + 2 < KT) load_stage((kt + 2) % STAGES, (kt + 2) * BK);

        __half* As = sh + (kt % STAGES) * STAGE_HALVES;
        __half* Bs = As + A_ST_HALVES;
#pragma unroll
        for (int kk = 0; kk < BK; kk += 16) {
            wmma::fragment<wmma::matrix_a, 16, 16, 16, __half, wmma::row_major> af[4];
            wmma::fragment<wmma::matrix_b, 16, 16, 16, __half, wmma::row_major> bf[2];
#pragma unroll
            for (int i = 0; i < 4; i++)
                wmma::load_matrix_sync(af[i], As + (wm * 64 + i * 16) * A_PITCH + kk, A_PITCH);
#pragma unroll
            for (int j = 0; j < 2; j++)
                wmma::load_matrix_sync(bf[j], Bs + kk * B_PITCH + wn * 32 + j * 16, B_PITCH);
#pragma unroll
            for (int i = 0; i < 4; i++)
#pragma unroll
                for (int j = 0; j < 2; j++)
                    wmma::mma_sync(acc[i][j], af[i], bf[j], acc[i][j]);
        }
        __syncthreads();
    }

    // epilogue in two 64-col halves via shared (Cs: 128 x 68 floats = 34.8KB)
    float* Cs = (float*)smem;
#pragma unroll
    for (int h = 0; h < 2; h++) {
        __syncthreads();
        if ((wn >> 1) == h) {
#pragma unroll
            for (int i = 0; i < 4; i++)
#pragma unroll
                for (int j = 0; j < 2; j++)
                    wmma::store_matrix_sync(
                        Cs + (wm * 64 + i * 16) * 68 + (wn & 1) * 32 + j * 16,
                        acc[i][j], 68, wmma::mem_row_major);
        }
        __syncthreads();
#pragma unroll
        for (int l = 0; l < 32; l++) {
            int i = tid + l * 256;          // 8192 = 128x64
            int r = i >> 6, c = i & 63;
            float v = Cs[r * 68 + c];
            int R = m0 + r;
            int C = n0 + h * 64 + c;
            if (MODE == 0) {
                float rl = fmaxf(v, 0.f);
                g_ActS[(size_t)R * SH_I + C] = __float2half(rl * rl);
            }
            if (MODE == 1) {
                out[(size_t)R * HID + C] = v;
            }
            if (MODE == 2) {
                float rl = fmaxf(v, 0.f);
                g_Act[(size_t)R * MOE_I + C] = __float2half(rl * rl * g_pw[R]);
            }
            if (MODE == 3) {
                atomicAdd(out + (size_t)g_perm[R] * HID + C, v);
            }
        }
    }
}

// ---------------- launch (single stream; gemm1 is launch index 5 for ncu) ----------------
extern "C" void kernel_launch(void* const* d_in, const int* in_sizes, int n_in,
                              void* d_out, int out_size)
{
    const float* x  = (const float*)d_in[0];
    const float* wr = (const float*)d_in[1];
    const float* eb = (const float*)d_in[2];
    const float* wu = (const float*)d_in[3];
    const float* wd = (const float*)d_in[4];
    const float* su = (const float*)d_in[5];
    const float* sd = (const float*)d_in[6];
    float* out = (float*)d_out;

    cudaFuncSetAttribute(gemm_kernel<0>, cudaFuncAttributeMaxDynamicSharedMemorySize, GEMM_SMEM_BYTES);
    cudaFuncSetAttribute(gemm_kernel<1>, cudaFuncAttributeMaxDynamicSharedMemorySize, GEMM_SMEM_BYTES);
    cudaFuncSetAttribute(gemm_kernel<2>, cudaFuncAttributeMaxDynamicSharedMemorySize, GEMM_SMEM_BYTES);
    cudaFuncSetAttribute(gemm_kernel<3>, cudaFuncAttributeMaxDynamicSharedMemorySize, GEMM_SMEM_BYTES);

    __half* wu16p; cudaGetSymbolAddress((void**)&wu16p, g_wu16);
    __half* wd16p; cudaGetSymbolAddress((void**)&wd16p, g_wd16);
    __half* su16p; cudaGetSymbolAddress((void**)&su16p, g_su16);
    __half* sd16p; cudaGetSymbolAddress((void**)&sd16p, g_sd16);

    const int n8_sd = SH_I * HID / 8;
    const int n8_wu = NEXP * HID * MOE_I / 8;
    const int n8_wd = NEXP * MOE_I * HID / 8;

    cvtw_kernel<<<4096, 256>>>(su, su16p, HID * SH_I / 8);   // 0
    router_kernel<<<T_TOK / 4, 128>>>(x, wr, eb);            // 1
    gather_kernel<<<NEXP, 256>>>();                          // 2 (scan fused)
    convx_kernel<<<T_TOK, 256>>>(x);                         // 3

    // 4: gemm0 (+ convert sd on z=1, gatherx on z=2)
    gemm_kernel<0><<<dim3(SH_I / BN, T_TOK / BM, 3), 256, GEMM_SMEM_BYTES>>>(
        su16p, out, sd, sd16p, n8_sd);
    // 5: gemm1 (+ convert wu)  <- ncu -s 5 -c 1 capture slot
    gemm_kernel<1><<<dim3(HID / BN, T_TOK / BM, 2), 256, GEMM_SMEM_BYTES>>>(
        sd16p, out, wu, wu16p, n8_wu);
    // 6: gemm2 (+ convert wd)
    gemm_kernel<2><<<dim3(MOE_I / BN, MAX_TILES, 2), 256, GEMM_SMEM_BYTES>>>(
        wu16p, out, wd, wd16p, n8_wd);
    // 7: gemm3
    gemm_kernel<3><<<dim3(HID / BN, MAX_TILES, 1), 256, GEMM_SMEM_BYTES>>>(
        wd16p, out, (const float*)nullptr, (__half*)nullptr, 0);
}